// round 13
// baseline (speedup 1.0000x reference)
#include <cuda_runtime.h>
#include <math.h>
#include <stdint.h>

#define WAY   100
#define SHOT  5
#define DIM   2048
#define NQ    10000
#define KSEL  512
#define TQ    64
#define TKC   32
#define NT    157
#define BSS   113
#define SLAB  (112*NT)

// ---------------- static scratch ----------------
#define SLP (WAY*DIM)
#define O_P0   0
#define O_P1   (O_P0 + 2*SLP)
#define O_QN   (O_P1 + 4*SLP)
#define O_G    (O_QN + 2*NQ)
#define O_L    (O_G  + 2*NQ*WAY)
#define O_CERT (O_L  + 4*NQ*WAY)
#define O_SELV (O_CERT + 4*NQ)
#define O_STAT (O_SELV + 4*KSEL)
#define O_SC1  (O_STAT + 4*NQ)
#define O_SC2  (O_SC1 + 4*WAY)
#define O_KL   (O_SC2 + 4*WAY)
#define O_PART (O_KL + 2*WAY)
#define TOTF   (O_PART + 4*SLAB)
__device__ float g_buf[TOTF];

#define IO_RES  0
#define IO_DCT  NQ
#define IO_SELI (2*NQ)
#define IO_PSE  (2*NQ+4*KSEL)
#define IO_SELK (2*NQ+8*KSEL)
#define IO_CNTS (2*NQ+8*KSEL+4)
#define IO_TICK (2*NQ+8*KSEL+6)   // [0..1] classkl tickets, [2..5] cert/topk tickets
__device__ int g_ibuf[2*NQ+8*KSEL+12];
__device__ int g_fullCnt = NQ;

// ---------------- job structs ----------------
struct GJob { const float* A; const float* qn; const float* P; float* C;
              float* part; const int* map; const int* cnt; int transC; };
struct GJobs { GJob j[4]; };
struct JSet {
    const float* A[4]; const float* qn[4]; const float* P0[4]; const float* G[4];
    const int* map[4]; const int* cnt[4];
    float* P1[4]; float* cert[4]; float* selv[4]; float* sc1[4]; float* sc2[4];
    int* seli[4]; int* selk[4]; int* pse[4];
    const float* part[4];
};
struct RSJ { const float* L[2]; const float* sc[2]; float* absc[2]; float* relc[2]; };
struct KLJ { const float* Lh[2]; const float* Ll[2]; const float* ph[2];
             const float* pl[2]; const int* cnt[2]; float* kl[2]; const float* tp;
             const float* absc[2]; const int* idx[2]; const float* tsc[2];
             float* slot[2]; int* tick; };

// ---------------- reductions ----------------
__device__ __forceinline__ float bSum256(float v, float* s) {
    int t = threadIdx.x; __syncthreads(); s[t] = v; __syncthreads();
    #pragma unroll
    for (int o = 128; o > 0; o >>= 1) { if (t < o) s[t] += s[t+o]; __syncthreads(); }
    float r = s[0]; __syncthreads(); return r;
}
__device__ __forceinline__ float bMax256(float v, float* s) {
    int t = threadIdx.x; __syncthreads(); s[t] = v; __syncthreads();
    #pragma unroll
    for (int o = 128; o > 0; o >>= 1) { if (t < o) s[t] = fmaxf(s[t], s[t+o]); __syncthreads(); }
    float r = s[0]; __syncthreads(); return r;
}
__device__ __forceinline__ int bScan1024(int v, int* tot, int* ws) {
    int t = threadIdx.x, lane = t & 31, w = t >> 5, x = v;
    #pragma unroll
    for (int o = 1; o < 32; o <<= 1) { int y = __shfl_up_sync(~0u, x, o); if (lane >= o) x += y; }
    if (lane == 31) ws[w] = x;
    __syncthreads();
    if (w == 0) {
        int s2 = ws[lane];
        #pragma unroll
        for (int o = 1; o < 32; o <<= 1) { int y = __shfl_up_sync(~0u, s2, o); if (lane >= o) s2 += y; }
        ws[lane] = s2;
    }
    __syncthreads();
    int r = (w ? ws[w-1] : 0) + x - v; *tot = ws[31]; __syncthreads(); return r;
}
__device__ __forceinline__ unsigned okey(float f) {
    unsigned u = __float_as_uint(f);
    return (u & 0x80000000u) ? ~u : (u | 0x80000000u);
}

// ------- merged proto0 + qnorm (+ticket reset for phase-1 cert/topk) -------
__global__ void k_init(const float* __restrict__ s0, const float* __restrict__ s1,
                       const float* __restrict__ x0, const float* __restrict__ x1,
                       float* __restrict__ p0, float* __restrict__ p1,
                       float* __restrict__ q0, float* __restrict__ q1,
                       int* __restrict__ tick) {
    int job = blockIdx.y;
    __shared__ float red[256];
    if (blockIdx.x == 0 && job == 0 && threadIdx.x < 2) tick[2 + threadIdx.x] = 0;
    if (blockIdx.x < WAY) {
        const float* shot = job ? s1 : s0;
        float* proto = job ? p1 : p0;
        int c = blockIdx.x;
        const float4* sB = (const float4*)(shot + (size_t)c*SHOT*DIM);
        float4* pB = (float4*)(proto + (size_t)c*DIM);
        float ssq = 0.f;
        for (int d = threadIdx.x; d < DIM/4; d += 256) {
            float4 a = make_float4(0,0,0,0);
            #pragma unroll
            for (int s = 0; s < SHOT; s++) {
                float4 v = sB[s*(DIM/4)+d];
                a.x += v.x; a.y += v.y; a.z += v.z; a.w += v.w;
            }
            a.x *= 0.2f; a.y *= 0.2f; a.z *= 0.2f; a.w *= 0.2f;
            pB[d] = a;
            ssq += a.x*a.x + a.y*a.y + a.z*a.z + a.w*a.w;
        }
        float tot = bSum256(ssq, red);
        __shared__ float inv;
        if (threadIdx.x == 0) inv = 1.f / fmaxf(sqrtf(tot), 1e-12f);
        __syncthreads();
        for (int d = threadIdx.x; d < DIM/4; d += 256) {
            float4 a = pB[d]; a.x *= inv; a.y *= inv; a.z *= inv; a.w *= inv; pB[d] = a;
        }
    } else {
        const float* X = job ? x1 : x0;
        float* qn = job ? q1 : q0;
        int row = blockIdx.x - WAY;
        const float4* r4 = (const float4*)(X + (size_t)row*DIM);
        float ssq = 0.f;
        #pragma unroll
        for (int i = 0; i < 2; i++) {
            float4 v = r4[threadIdx.x + 256*i];
            ssq += v.x*v.x + v.y*v.y + v.z*v.z + v.w*v.w;
        }
        float tot = bSum256(ssq, red);
        if (threadIdx.x == 0) qn[row] = fmaxf(sqrtf(tot), 1e-12f);
    }
}

// ---------------- GEMM (optional transposed C output) ----------------
__global__ __launch_bounds__(256) void k_gemm(GJobs g) {
    __shared__ float4 As4[TQ][8];
    __shared__ float Bs[TKC][BSS];
    __shared__ int rowIdx[TQ];
    __shared__ float rowInv[TQ];
    float* tmp = (float*)As4;

    int job = blockIdx.x / NT, tb = blockIdx.x - job*NT;
    GJob J = g.j[job];
    int Q = *J.cnt;
    int rowBase = tb * TQ;
    if (rowBase >= Q) return;

    int t = threadIdx.x, tx = t & 15, ty = t >> 4;

    for (int i = t; i < TKC*13; i += 256) Bs[i/13][100 + i%13] = 0.f;
    if (t < TQ) {
        int j = rowBase + t; int gq = 0; float iv = 0.f;
        if (j < Q) { gq = J.map ? J.map[j] : j; iv = 1.f / J.qn[gq]; }
        rowIdx[t] = gq; rowInv[t] = iv;
    }
    __syncthreads();

    int r0 = t >> 3, k4 = t & 7;
    const float4* aP0 = (const float4*)(J.A + (size_t)rowIdx[r0]*DIM) + k4;
    const float4* aP1 = (const float4*)(J.A + (size_t)rowIdx[r0+32]*DIM) + k4;
    int f1 = t, f2 = t+256, f3 = t+512, f4 = t+768;
    const float4* bP1 = (const float4*)(J.P + (size_t)(f1>>3)*DIM) + (f1&7);
    const float4* bP2 = (const float4*)(J.P + (size_t)(f2>>3)*DIM) + (f2&7);
    const float4* bP3 = (const float4*)(J.P + (size_t)(f3>>3)*DIM) + (f3&7);
    const float4* bP4 = (f4 < 800) ? (const float4*)(J.P + (size_t)(f4>>3)*DIM) + (f4&7) : bP1;
    bool act4 = (f4 < 800);

    float acc[4][7];
    #pragma unroll
    for (int i = 0; i < 4; i++)
        #pragma unroll
        for (int jj = 0; jj < 7; jj++) acc[i][jj] = 0.f;

    float4 pa0 = aP0[0], pa1 = aP1[0];
    float4 pb1 = bP1[0], pb2 = bP2[0], pb3 = bP3[0], pb4 = act4 ? bP4[0] : make_float4(0,0,0,0);

    for (int k0 = 0; k0 < DIM; k0 += TKC) {
        As4[r0][k4] = pa0; As4[r0+32][k4] = pa1;
        {
            int kb = (f1&7)*4, c = f1>>3;
            Bs[kb+0][c]=pb1.x; Bs[kb+1][c]=pb1.y; Bs[kb+2][c]=pb1.z; Bs[kb+3][c]=pb1.w;
            kb = (f2&7)*4; c = f2>>3;
            Bs[kb+0][c]=pb2.x; Bs[kb+1][c]=pb2.y; Bs[kb+2][c]=pb2.z; Bs[kb+3][c]=pb2.w;
            kb = (f3&7)*4; c = f3>>3;
            Bs[kb+0][c]=pb3.x; Bs[kb+1][c]=pb3.y; Bs[kb+2][c]=pb3.z; Bs[kb+3][c]=pb3.w;
            if (act4) {
                kb = (f4&7)*4; c = f4>>3;
                Bs[kb+0][c]=pb4.x; Bs[kb+1][c]=pb4.y; Bs[kb+2][c]=pb4.z; Bs[kb+3][c]=pb4.w;
            }
        }
        __syncthreads();
        if (k0 + TKC < DIM) {
            int off = (k0 + TKC) >> 2;
            pa0 = aP0[off]; pa1 = aP1[off];
            pb1 = bP1[off]; pb2 = bP2[off]; pb3 = bP3[off];
            if (act4) pb4 = bP4[off];
        }
        #pragma unroll
        for (int kk4 = 0; kk4 < 8; kk4++) {
            float4 A0 = As4[ty*4+0][kk4], A1 = As4[ty*4+1][kk4];
            float4 A2 = As4[ty*4+2][kk4], A3 = As4[ty*4+3][kk4];
            float a0v[4] = {A0.x,A0.y,A0.z,A0.w};
            float a1v[4] = {A1.x,A1.y,A1.z,A1.w};
            float a2v[4] = {A2.x,A2.y,A2.z,A2.w};
            float a3v[4] = {A3.x,A3.y,A3.z,A3.w};
            #pragma unroll
            for (int s = 0; s < 4; s++) {
                const float* br = &Bs[kk4*4+s][tx*7];
                #pragma unroll
                for (int jj = 0; jj < 7; jj++) {
                    float b = br[jj];
                    acc[0][jj] += a0v[s]*b;
                    acc[1][jj] += a1v[s]*b;
                    acc[2][jj] += a2v[s]*b;
                    acc[3][jj] += a3v[s]*b;
                }
            }
        }
        __syncthreads();
    }

    float colssq[7];
    #pragma unroll
    for (int jj = 0; jj < 7; jj++) colssq[jj] = 0.f;
    #pragma unroll
    for (int i = 0; i < 4; i++) {
        int j = rowBase + ty*4 + i;
        float iv = rowInv[ty*4 + i];
        float v[7];
        #pragma unroll
        for (int jj = 0; jj < 7; jj++) { v[jj] = acc[i][jj]*iv; colssq[jj] += v[jj]*v[jj]; }
        if (j < Q) {
            if (J.transC) {
                #pragma unroll
                for (int jj = 0; jj < 7; jj++) {
                    int c = tx*7 + jj;
                    if (c < WAY) J.C[(size_t)c*NQ + j] = v[jj];
                }
            } else {
                #pragma unroll
                for (int jj = 0; jj < 7; jj++) {
                    int c = tx*7 + jj;
                    if (c < WAY) J.C[(size_t)j*WAY + c] = v[jj];
                }
            }
        }
    }
    #pragma unroll
    for (int jj = 0; jj < 7; jj++) tmp[ty*112 + tx*7+jj] = colssq[jj];
    __syncthreads();
    if (t < 112) {
        float s = 0.f;
        #pragma unroll
        for (int r = 0; r < 16; r++) s += tmp[r*112 + t];
        J.part[(size_t)t*NT + tb] = s;
    }
}

// ---- reduce partials -> scale ----
__global__ void k_colreduce(JSet js, const float* __restrict__ tp,
                            int useSc2, int fixedNT) {
    int job = blockIdx.x, t = threadIdx.x;
    if (t >= WAY) return;
    int nT = fixedNT ? fixedNT : (*js.cnt[job] + TQ - 1) / TQ;
    const float* p = js.part[job] + (size_t)t*NT;
    float s = 0.f;
    #pragma unroll 16
    for (int tb = 0; tb < nT; tb++) s += p[tb];
    float* o = useSc2 ? js.sc2[job] : js.sc1[job];
    o[t] = (*tp) / (sqrtf(s) + 1e-6f);
}

// ------- merged subset colnorm partials + partition + weights (+ticket reset) -------
__global__ __launch_bounds__(1024) void k_subpartition(
    const float* __restrict__ Gr, const float* __restrict__ Gd,
    const float* __restrict__ ar, const float* __restrict__ ad,
    const float* __restrict__ rr, const float* __restrict__ rd,
    float* __restrict__ part,
    int* __restrict__ resI, int* __restrict__ dctI,
    int* __restrict__ cnts, int* __restrict__ tick, float* __restrict__ out)
{
    int t = threadIdx.x;
    if (blockIdx.y < 2) {
        if (t >= 128) return;
        int tile = blockIdx.x, s = blockIdx.y;
        int c = t;
        const float* G = s ? Gd : Gr;
        float sR = 0.f, sD = 0.f;
        int j0 = tile * TQ;
        int jend = j0 + TQ; if (jend > NQ) jend = NQ;
        for (int j = j0; j < jend; j++) {
            float diff = ar[j] - ad[j] + rr[j] - rd[j];
            float v = (c < WAY) ? G[(size_t)j*WAY + c] : 0.f;
            float v2 = v*v;
            if (diff > 0.f) sR += v2;
            if (diff < 0.f) sD += v2;
        }
        if (c < 112) {
            part[(size_t)(2*s+0)*SLAB + (size_t)c*NT + tile] = sR;
            part[(size_t)(2*s+1)*SLAB + (size_t)c*NT + tile] = sD;
        }
        return;
    }
    if (blockIdx.x != 0) return;
    __shared__ int ws[32];
    __shared__ int rb, Rs;
    if (t < 6) tick[t] = 0;
    if (t == 0) rb = 0;
    __syncthreads();
    for (int j0 = 0; j0 < NQ; j0 += 1024) {
        int j = j0 + t, f = 0;
        if (j < NQ) f = ((ar[j]-ad[j]+rr[j]-rd[j]) > 0.f);
        int tot; int ex = bScan1024(f, &tot, ws);
        if (f) { int sl = rb + ex; resI[sl] = j; out[2+sl] = (float)j; }
        __syncthreads();
        if (t == 0) rb += tot;
        __syncthreads();
    }
    if (t == 0) { Rs = rb; cnts[0] = rb; rb = 0; }
    __syncthreads();
    int R = Rs;
    for (int j0 = 0; j0 < NQ; j0 += 1024) {
        int j = j0 + t, f = 0;
        if (j < NQ) f = ((ar[j]-ad[j]+rr[j]-rd[j]) < 0.f);
        int tot; int ex = bScan1024(f, &tot, ws);
        if (f) { int sl = rb + ex; dctI[sl] = j; out[2+R+sl] = (float)j; }
        __syncthreads();
        if (t == 0) rb += tot;
        __syncthreads();
    }
    if (t == 0) cnts[1] = rb;
    __syncthreads();
    int base = 2 + R + rb;
    for (int q = t; q < NQ; q += 1024) {
        float a = ar[q], b = ad[q], den = fmaxf(a+b, 1e-8f);
        out[base + q] = a/den;
        out[base + NQ + q] = b/den;
    }
}

// ------- fused cert + topk: blocks x<10 cert, block x==10 topk (ticket-ordered) -------
__global__ __launch_bounds__(1024) void k_certtopk(JSet js, const float* __restrict__ tp,
                                                   int* __restrict__ ct) {
    int job = blockIdx.y, t = threadIdx.x;
    int Q = *js.cnt[job];
    if (blockIdx.x < 10) {
        int jbase = blockIdx.x * 1024;
        __shared__ float ssc[WAY];
        if (jbase < Q || blockIdx.x == 0) {
            if (t < WAY) {
                const float* p = js.part[job] + (size_t)t*NT;
                float s = 0.f;
                #pragma unroll 16
                for (int tb = 0; tb < NT; tb++) s += p[tb];
                float sc = (*tp) / (sqrtf(s) + 1e-6f);
                ssc[t] = sc;
                if (blockIdx.x == 0) js.sc1[job][t] = sc;
            }
            __syncthreads();
            int j = jbase + t;
            if (j < Q) {
                const int* map = js.map[job];
                int r = map ? map[j] : j;
                const float* row = js.G[job] + (size_t)r*WAY;
                float best = -3.4e38f;
                #pragma unroll 4
                for (int c = 0; c < WAY; c++) { float v = row[c]*ssc[c]; if (v > best) best = v; }
                js.cert[job][j] = best;
            }
        }
        __threadfence();
        __syncthreads();
        if (t == 0) atomicAdd(&ct[job], 1);
        return;
    }
    // topk block: wait for all 10 cert blocks
    if (t == 0) { while (atomicAdd(&ct[job], 0) < 10) { } }
    __syncthreads();
    __threadfence();
    const float* cert = js.cert[job];
    __shared__ unsigned hist[2048];
    __shared__ int ws[32];
    __shared__ unsigned shP, shM;
    __shared__ int shR;
    __shared__ float ssc2[WAY];
    int k = (Q < KSEL) ? Q : KSEL;
    if (t == 0) { shP = 0u; shM = 0u; shR = k; }
    __syncthreads();
    for (int pass = 0; pass < 3; pass++) {
        int shift = (pass == 0) ? 21 : ((pass == 1) ? 10 : 0);
        int nb = (pass == 2) ? 1024 : 2048;
        for (int i = t; i < 2048; i += 1024) hist[i] = 0u;
        __syncthreads();
        unsigned pfx = shP, msk = shM;
        int rem = shR;
        for (int j = t; j < Q; j += 1024) {
            unsigned u = okey(cert[j]);
            if ((u & msk) == pfx) atomicAdd(&hist[(u >> shift) & (nb-1)], 1u);
        }
        __syncthreads();
        int i0 = nb - 1 - 2*t, i1 = nb - 2 - 2*t;
        int h0 = (i0 >= 0) ? (int)hist[i0] : 0;
        int h1 = (i1 >= 0) ? (int)hist[i1] : 0;
        int tot; int ex = bScan1024(h0 + h1, &tot, ws);
        if (i0 >= 0 && ex < rem && ex + h0 >= rem) {
            shP = pfx | ((unsigned)i0 << shift);
            shM = msk | ((unsigned)(nb-1) << shift);
            shR = rem - ex;
        } else if (i1 >= 0 && ex + h0 < rem && ex + h0 + h1 >= rem) {
            shP = pfx | ((unsigned)i1 << shift);
            shM = msk | ((unsigned)(nb-1) << shift);
            shR = rem - ex - h0;
        }
        __syncthreads();
    }
    unsigned Kk = shP; int rem = shR;
    // selection: 4 consecutive elements/thread (measured-best form)
    int eqB = 0, seB = 0;
    for (int j0 = 0; j0 < Q; j0 += 4096) {
        int jb = j0 + t*4;
        int gi[4], ei[4]; float vi[4];
        int gcnt = 0, ecnt = 0;
        #pragma unroll
        for (int i = 0; i < 4; i++) {
            int j = jb + i;
            gi[i] = 0; ei[i] = 0; vi[i] = 0.f;
            if (j < Q) {
                float v = cert[j];
                unsigned u = okey(v);
                gi[i] = (u > Kk); ei[i] = (u == Kk); vi[i] = v;
            }
            gcnt += gi[i]; ecnt += ei[i];
        }
        int tot; int ex = bScan1024(gcnt | (ecnt << 13), &tot, ws);
        int gEx = ex & 0x1FFF, eEx = ex >> 13;
        int gTot = tot & 0x1FFF, eTot = tot >> 13;
        int c0 = rem - eqB; if (c0 < 0) c0 = 0;
        int gP = 0, eP = 0;
        #pragma unroll
        for (int i = 0; i < 4; i++) {
            int er = eEx + eP;
            int eqSelB = (er < c0) ? er : c0;
            int sel = gi[i] | (ei[i] & (er < c0));
            if (sel) {
                int sl = seB + gEx + gP + eqSelB;
                js.seli[job][sl] = jb + i;
                js.selv[job][sl] = vi[i];
            }
            gP += gi[i]; eP += ei[i];
        }
        eqB += eTot;
        seB += gTot + ((eTot < c0) ? eTot : c0);
    }
    if (t == 0) *js.selk[job] = k;
    if (t < WAY) ssc2[t] = js.sc1[job][t];
    __syncthreads();
    const int* map = js.map[job];
    for (int i = t; i < k; i += 1024) {
        int j = js.seli[job][i];
        int r = map ? map[j] : j;
        const float* row = js.G[job] + (size_t)r*WAY;
        float best = -3.4e38f; int bc = 0;
        for (int c = 0; c < WAY; c++) { float v = row[c]*ssc2[c]; if (v > best) { best = v; bc = c; } }
        js.pse[job][i] = bc;
    }
}

// ---------------- refined proto ----------------
__global__ void k_proto1(JSet js) {
    int job = blockIdx.y, c = blockIdx.x;
    int K = *js.selk[job];
    __shared__ int sQ[KSEL], sP[KSEL];
    __shared__ float sC[KSEL];
    const int* map = js.map[job];
    for (int i = threadIdx.x; i < K; i += 256) {
        int j = js.seli[job][i];
        int gq = map ? map[j] : j;
        sQ[i] = gq; sP[i] = js.pse[job][i];
        sC[i] = js.selv[job][i] / ((float)K * js.qn[job][gq]);
    }
    __syncthreads();
    const float* P0 = js.P0[job] + (size_t)c*DIM;
    float* P1 = js.P1[job] + (size_t)c*DIM;
    const float* A = js.A[job];
    int t = threadIdx.x;
    float acc[8];
    #pragma unroll
    for (int kq = 0; kq < 8; kq++) acc[kq] = P0[t + 256*kq];
    for (int i = 0; i < K; i++) {
        if (sP[i] == c) {
            float cf = sC[i];
            const float* a = A + (size_t)sQ[i]*DIM;
            #pragma unroll
            for (int kq = 0; kq < 8; kq++) acc[kq] += cf * a[t + 256*kq];
        }
    }
    #pragma unroll
    for (int kq = 0; kq < 8; kq++) P1[t + 256*kq] = acc[kq];
}

// ---------------- row softmax stats ----------------
__global__ void k_rowstats(RSJ r) {
    int job = blockIdx.y;
    __shared__ float ssc[WAY];
    if (threadIdx.x < WAY) ssc[threadIdx.x] = r.sc[job][threadIdx.x];
    __syncthreads();
    int row = blockIdx.x*8 + (threadIdx.x >> 5);
    int lane = threadIdx.x & 31;
    if (row >= NQ) return;
    const float* L = r.L[job] + (size_t)row*WAY;
    float lv[4];
    int nc = 0;
    #pragma unroll
    for (int i = 0; i < 4; i++) {
        int c = lane + 32*i;
        if (c < WAY) { lv[i] = L[c]*ssc[c]; nc = i+1; } else lv[i] = 0.f;
    }
    float m = -3.4e38f;
    for (int i = 0; i < nc; i++) m = fmaxf(m, lv[i]);
    #pragma unroll
    for (int o = 16; o; o >>= 1) m = fmaxf(m, __shfl_xor_sync(~0u, m, o));
    float ex[4];
    float Z = 0.f;
    for (int i = 0; i < nc; i++) { ex[i] = expf(lv[i] - m); Z += ex[i]; }
    #pragma unroll
    for (int o = 16; o; o >>= 1) Z += __shfl_xor_sync(~0u, Z, o);
    float rel = 0.f;
    for (int i = 0; i < nc; i++) {
        float p = ex[i] / Z;
        rel += p * logf(p + 1e-10f);
    }
    #pragma unroll
    for (int o = 16; o; o >>= 1) rel += __shfl_xor_sync(~0u, rel, o);
    if (lane == 0) { r.absc[job][row] = m; r.relc[job][row] = rel; }
}

// ------- per-class KL (transposed L) + fused last-block finalize -------
__global__ void k_classkl(KLJ kj) {
    int pr = blockIdx.y, c = blockIdx.x;
    int Q = *kj.cnt[pr];
    int nT = (Q + TQ - 1) / TQ;
    __shared__ float shsl[2];
    __shared__ float red[256];
    if (threadIdx.x < 2) {
        const float* p = (threadIdx.x ? kj.pl[pr] : kj.ph[pr]) + (size_t)c*NT;
        float s = 0.f;
        #pragma unroll 16
        for (int tb = 0; tb < nT; tb++) s += p[tb];
        shsl[threadIdx.x] = (*kj.tp) / (sqrtf(s) + 1e-6f);
    }
    __syncthreads();
    float sh = shsl[0], sl = shsl[1];
    const float* Lh = kj.Lh[pr] + (size_t)c*NQ;
    const float* Ll = kj.Ll[pr] + (size_t)c*NQ;
    float mh = -3.4e38f, ml = -3.4e38f;
    for (int j = threadIdx.x; j < Q; j += 256) {
        mh = fmaxf(mh, Lh[j]*sh);
        ml = fmaxf(ml, Ll[j]*sl);
    }
    mh = bMax256(mh, red); ml = bMax256(ml, red);
    float Zh = 0.f, Zl = 0.f;
    for (int j = threadIdx.x; j < Q; j += 256) {
        Zh += expf(Lh[j]*sh - mh);
        Zl += expf(Ll[j]*sl - ml);
    }
    Zh = bSum256(Zh, red); Zl = bSum256(Zl, red);
    float lZl = logf(Zl), s = 0.f;
    for (int j = threadIdx.x; j < Q; j += 256) {
        float lh = Lh[j]*sh, ll = Ll[j]*sl;
        float p = expf(lh - mh) / Zh;
        s += p * (logf(p) - (ll - ml - lZl));
    }
    s = bSum256(s, red);
    __shared__ int isLast;
    if (threadIdx.x == 0) {
        kj.kl[pr][c] = s;
        __threadfence();
        int old = atomicAdd(&kj.tick[pr], 1);
        isLast = (old == WAY - 1);
    }
    __syncthreads();
    if (!isLast) return;
    __threadfence();
    float fs = 0.f;
    for (int cc = threadIdx.x; cc < WAY; cc += 256) fs += kj.kl[pr][cc];
    fs = bSum256(fs, red);
    float sw = 0.f;
    for (int j = threadIdx.x; j < Q; j += 256) sw += kj.absc[pr][kj.idx[pr][j]];
    sw = bSum256(sw, red);
    if (threadIdx.x == 0) {
        float w0 = (Q > 0) ? kj.absc[pr][kj.idx[pr][0]] : 0.f;
        *kj.slot[pr] = (*kj.tsc[pr]) * (w0 * fs / (sw + 1e-8f));
    }
}

// ---------------- host ----------------
extern "C" void kernel_launch(void* const* d_in, const int* in_sizes, int n_in,
                              void* d_out, int out_size)
{
    const float* x_shot    = (const float*)d_in[0];
    const float* x_query   = (const float*)d_in[1];
    const float* dct_shot  = (const float*)d_in[2];
    const float* dct_query = (const float*)d_in[3];
    const float* tp        = (const float*)d_in[4];
    const float* temp      = (const float*)d_in[5];
    const float* temp_dct  = (const float*)d_in[6];
    float* out = (float*)d_out;

    float* B = nullptr; int* IB = nullptr; int* FC = nullptr;
    cudaGetSymbolAddress((void**)&B, g_buf);
    cudaGetSymbolAddress((void**)&IB, g_ibuf);
    cudaGetSymbolAddress((void**)&FC, g_fullCnt);

    float* P0 = B + O_P0;     float* P1 = B + O_P1;
    float* QN = B + O_QN;     float* G = B + O_G;
    float* L = B + O_L;       float* CERT = B + O_CERT;
    float* SELV = B + O_SELV;
    float* ABSR = B + O_STAT; float* ABSD = ABSR + NQ;
    float* RELR = ABSD + NQ;  float* RELD = RELR + NQ;
    float* SC1 = B + O_SC1;   float* SC2 = B + O_SC2;
    float* KL = B + O_KL;     float* PART = B + O_PART;
    int* RES = IB + IO_RES;   int* DCT = IB + IO_DCT;
    int* SELI = IB + IO_SELI; int* PSE = IB + IO_PSE;
    int* SELK = IB + IO_SELK; int* CNTS = IB + IO_CNTS;
    int* TICK = IB + IO_TICK;
    int* CT   = TICK + 2;
    const int* CR = CNTS;     const int* CD = CNTS + 1;

    const float* Aq[2] = { x_query, dct_query };

    // -------- phase 1 --------
    JSet j1 = {};
    for (int s = 0; s < 2; s++) {
        j1.A[s] = Aq[s]; j1.qn[s] = QN + s*NQ;
        j1.P0[s] = P0 + s*SLP; j1.G[s] = G + (size_t)s*NQ*WAY;
        j1.map[s] = nullptr; j1.cnt[s] = FC;
        j1.P1[s] = P1 + s*SLP;
        j1.cert[s] = CERT + s*NQ; j1.selv[s] = SELV + s*KSEL;
        j1.sc1[s] = SC1 + s*WAY; j1.sc2[s] = SC2 + s*WAY;
        j1.seli[s] = SELI + s*KSEL; j1.selk[s] = SELK + s; j1.pse[s] = PSE + s*KSEL;
        j1.part[s] = PART + (size_t)s*SLAB;
    }
    k_init<<<dim3(WAY + NQ, 2), 256>>>(x_shot, dct_shot, x_query, dct_query,
                                       P0, P0 + SLP, QN, QN + NQ, TICK);

    GJobs g1 = {};
    for (int s = 0; s < 2; s++)
        g1.j[s] = { Aq[s], QN + s*NQ, P0 + s*SLP, G + (size_t)s*NQ*WAY,
                    PART + (size_t)s*SLAB, nullptr, FC, 0 };
    k_gemm<<<2*NT, 256>>>(g1);
    k_certtopk<<<dim3(11, 2), 1024>>>(j1, tp, CT);
    k_proto1<<<dim3(WAY,2), 256>>>(j1);

    GJobs g2 = {};
    for (int s = 0; s < 2; s++)
        g2.j[s] = { Aq[s], QN + s*NQ, P1 + s*SLP, L + (size_t)s*NQ*WAY,
                    PART + (size_t)s*SLAB, nullptr, FC, 0 };
    k_gemm<<<2*NT, 256>>>(g2);
    k_colreduce<<<2, 128>>>(j1, tp, 1, 0);

    RSJ rs;
    rs.L[0] = L; rs.L[1] = L + (size_t)NQ*WAY;
    rs.sc[0] = SC2; rs.sc[1] = SC2 + WAY;
    rs.absc[0] = ABSR; rs.absc[1] = ABSD;
    rs.relc[0] = RELR; rs.relc[1] = RELD;
    k_rowstats<<<dim3((NQ+7)/8, 2), 256>>>(rs);

    k_subpartition<<<dim3(NT, 3), 1024>>>(G, G + (size_t)NQ*WAY,
                                          ABSR, ABSD, RELR, RELD,
                                          PART, RES, DCT, CNTS, TICK, out);

    // -------- phase 3: jobs 0 x/RES  1 dct/RES  2 dct/DCT  3 x/DCT --------
    int src[4] = { 0, 1, 1, 0 };
    const int* mp[4] = { RES, RES, DCT, DCT };
    const int* cn[4] = { CR, CR, CD, CD };
    int slab[4] = { 0, 2, 3, 1 };
    JSet j3 = {};
    for (int s = 0; s < 4; s++) {
        int u = src[s];
        j3.A[s] = Aq[u]; j3.qn[s] = QN + u*NQ;
        j3.P0[s] = P0 + u*SLP; j3.G[s] = G + (size_t)u*NQ*WAY;
        j3.map[s] = mp[s]; j3.cnt[s] = cn[s];
        j3.P1[s] = P1 + s*SLP;
        j3.cert[s] = CERT + s*NQ; j3.selv[s] = SELV + s*KSEL;
        j3.sc1[s] = SC1 + s*WAY; j3.sc2[s] = SC2 + s*WAY;
        j3.seli[s] = SELI + s*KSEL; j3.selk[s] = SELK + s; j3.pse[s] = PSE + s*KSEL;
        j3.part[s] = PART + (size_t)slab[s]*SLAB;
    }
    k_certtopk<<<dim3(11, 4), 1024>>>(j3, tp, CT);
    k_proto1<<<dim3(WAY,4), 256>>>(j3);

    GJobs g3 = {};
    for (int s = 0; s < 4; s++)
        g3.j[s] = { j3.A[s], j3.qn[s], P1 + s*SLP, L + (size_t)s*NQ*WAY,
                    PART + (size_t)s*SLAB, mp[s], cn[s], 1 };
    k_gemm<<<4*NT, 256>>>(g3);

    KLJ kj;
    kj.Lh[0] = L;                     kj.Ll[0] = L + (size_t)NQ*WAY;
    kj.ph[0] = PART;                  kj.pl[0] = PART + (size_t)1*SLAB;
    kj.cnt[0] = CR; kj.kl[0] = KL;
    kj.Lh[1] = L + (size_t)2*NQ*WAY;  kj.Ll[1] = L + (size_t)3*NQ*WAY;
    kj.ph[1] = PART + (size_t)2*SLAB; kj.pl[1] = PART + (size_t)3*SLAB;
    kj.cnt[1] = CD; kj.kl[1] = KL + WAY;
    kj.tp = tp;
    kj.absc[0] = ABSR; kj.idx[0] = RES; kj.tsc[0] = temp_dct; kj.slot[0] = out + 1;
    kj.absc[1] = ABSD; kj.idx[1] = DCT; kj.tsc[1] = temp;     kj.slot[1] = out + 0;
    kj.tick = TICK;
    k_classkl<<<dim3(WAY,2), 256>>>(kj);
}

// round 14
// speedup vs baseline: 1.1160x; 1.1160x over previous
#include <cuda_runtime.h>
#include <math.h>
#include <stdint.h>

#define WAY   100
#define SHOT  5
#define DIM   2048
#define NQ    10000
#define KSEL  512
#define TQ    64
#define TKC   32
#define NT    157
#define BSS   113
#define SLAB  (112*NT)

// ---------------- static scratch ----------------
#define SLP (WAY*DIM)
#define O_P0   0
#define O_P1   (O_P0 + 2*SLP)
#define O_QN   (O_P1 + 4*SLP)
#define O_G    (O_QN + 2*NQ)
#define O_L    (O_G  + 2*NQ*WAY)
#define O_CERT (O_L  + 4*NQ*WAY)
#define O_SELV (O_CERT + 4*NQ)
#define O_STAT (O_SELV + 4*KSEL)
#define O_SC1  (O_STAT + 4*NQ)
#define O_SC2  (O_SC1 + 4*WAY)
#define O_KL   (O_SC2 + 4*WAY)
#define O_PART (O_KL + 2*WAY)
#define TOTF   (O_PART + 4*SLAB)
__device__ float g_buf[TOTF];

#define IO_RES  0
#define IO_DCT  NQ
#define IO_SELI (2*NQ)
#define IO_PSE  (2*NQ+4*KSEL)
#define IO_SELK (2*NQ+8*KSEL)
#define IO_CNTS (2*NQ+8*KSEL+4)
#define IO_TICK (2*NQ+8*KSEL+6)
__device__ int g_ibuf[2*NQ+8*KSEL+8];
__device__ int g_fullCnt = NQ;

// ---------------- job structs ----------------
struct GJob { const float* A; const float* qn; const float* P; float* C;
              float* part; const int* map; const int* cnt; int transC; };
struct GJobs { GJob j[4]; };
struct JSet {
    const float* A[4]; const float* qn[4]; const float* P0[4]; const float* G[4];
    const int* map[4]; const int* cnt[4];
    float* P1[4]; float* cert[4]; float* selv[4]; float* sc1[4]; float* sc2[4];
    int* seli[4]; int* selk[4]; int* pse[4];
    const float* part[4];
};
struct RSJ { const float* L[2]; const float* sc[2]; float* absc[2]; float* relc[2]; };
struct KLJ { const float* Lh[2]; const float* Ll[2]; const float* ph[2];
             const float* pl[2]; const int* cnt[2]; float* kl[2]; const float* tp;
             const float* absc[2]; const int* idx[2]; const float* tsc[2];
             float* slot[2]; int* tick; };

// ---------------- reductions ----------------
__device__ __forceinline__ float bSum256(float v, float* s) {
    int t = threadIdx.x; __syncthreads(); s[t] = v; __syncthreads();
    #pragma unroll
    for (int o = 128; o > 0; o >>= 1) { if (t < o) s[t] += s[t+o]; __syncthreads(); }
    float r = s[0]; __syncthreads(); return r;
}
__device__ __forceinline__ float bMax256(float v, float* s) {
    int t = threadIdx.x; __syncthreads(); s[t] = v; __syncthreads();
    #pragma unroll
    for (int o = 128; o > 0; o >>= 1) { if (t < o) s[t] = fmaxf(s[t], s[t+o]); __syncthreads(); }
    float r = s[0]; __syncthreads(); return r;
}
__device__ __forceinline__ int bScan1024(int v, int* tot, int* ws) {
    int t = threadIdx.x, lane = t & 31, w = t >> 5, x = v;
    #pragma unroll
    for (int o = 1; o < 32; o <<= 1) { int y = __shfl_up_sync(~0u, x, o); if (lane >= o) x += y; }
    if (lane == 31) ws[w] = x;
    __syncthreads();
    if (w == 0) {
        int s2 = ws[lane];
        #pragma unroll
        for (int o = 1; o < 32; o <<= 1) { int y = __shfl_up_sync(~0u, s2, o); if (lane >= o) s2 += y; }
        ws[lane] = s2;
    }
    __syncthreads();
    int r = (w ? ws[w-1] : 0) + x - v; *tot = ws[31]; __syncthreads(); return r;
}
__device__ __forceinline__ int bScan256(int v, int* tot, int* ws) {
    int t = threadIdx.x, lane = t & 31, w = t >> 5, x = v;
    #pragma unroll
    for (int o = 1; o < 32; o <<= 1) { int y = __shfl_up_sync(~0u, x, o); if (lane >= o) x += y; }
    if (lane == 31) ws[w] = x;
    __syncthreads();
    if (w == 0 && lane < 8) {
        int s2 = ws[lane];
        #pragma unroll
        for (int o = 1; o < 8; o <<= 1) { int y = __shfl_up_sync(0xFFu, s2, o); if (lane >= o) s2 += y; }
        ws[lane] = s2;
    }
    __syncthreads();
    int r = (w ? ws[w-1] : 0) + x - v;
    *tot = ws[7];
    __syncthreads();
    return r;
}
__device__ __forceinline__ unsigned okey(float f) {
    unsigned u = __float_as_uint(f);
    return (u & 0x80000000u) ? ~u : (u | 0x80000000u);
}

// ------- merged proto0 + qnorm -------
__global__ void k_init(const float* __restrict__ s0, const float* __restrict__ s1,
                       const float* __restrict__ x0, const float* __restrict__ x1,
                       float* __restrict__ p0, float* __restrict__ p1,
                       float* __restrict__ q0, float* __restrict__ q1) {
    int job = blockIdx.y;
    __shared__ float red[256];
    if (blockIdx.x < WAY) {
        const float* shot = job ? s1 : s0;
        float* proto = job ? p1 : p0;
        int c = blockIdx.x;
        const float4* sB = (const float4*)(shot + (size_t)c*SHOT*DIM);
        float4* pB = (float4*)(proto + (size_t)c*DIM);
        float ssq = 0.f;
        for (int d = threadIdx.x; d < DIM/4; d += 256) {
            float4 a = make_float4(0,0,0,0);
            #pragma unroll
            for (int s = 0; s < SHOT; s++) {
                float4 v = sB[s*(DIM/4)+d];
                a.x += v.x; a.y += v.y; a.z += v.z; a.w += v.w;
            }
            a.x *= 0.2f; a.y *= 0.2f; a.z *= 0.2f; a.w *= 0.2f;
            pB[d] = a;
            ssq += a.x*a.x + a.y*a.y + a.z*a.z + a.w*a.w;
        }
        float tot = bSum256(ssq, red);
        __shared__ float inv;
        if (threadIdx.x == 0) inv = 1.f / fmaxf(sqrtf(tot), 1e-12f);
        __syncthreads();
        for (int d = threadIdx.x; d < DIM/4; d += 256) {
            float4 a = pB[d]; a.x *= inv; a.y *= inv; a.z *= inv; a.w *= inv; pB[d] = a;
        }
    } else {
        const float* X = job ? x1 : x0;
        float* qn = job ? q1 : q0;
        int row = blockIdx.x - WAY;
        const float4* r4 = (const float4*)(X + (size_t)row*DIM);
        float ssq = 0.f;
        #pragma unroll
        for (int i = 0; i < 2; i++) {
            float4 v = r4[threadIdx.x + 256*i];
            ssq += v.x*v.x + v.y*v.y + v.z*v.z + v.w*v.w;
        }
        float tot = bSum256(ssq, red);
        if (threadIdx.x == 0) qn[row] = fmaxf(sqrtf(tot), 1e-12f);
    }
}

// ---------------- GEMM (optional transposed C output) ----------------
__global__ __launch_bounds__(256) void k_gemm(GJobs g) {
    __shared__ float4 As4[TQ][8];
    __shared__ float Bs[TKC][BSS];
    __shared__ int rowIdx[TQ];
    __shared__ float rowInv[TQ];
    float* tmp = (float*)As4;

    int job = blockIdx.x / NT, tb = blockIdx.x - job*NT;
    GJob J = g.j[job];
    int Q = *J.cnt;
    int rowBase = tb * TQ;
    if (rowBase >= Q) return;

    int t = threadIdx.x, tx = t & 15, ty = t >> 4;

    for (int i = t; i < TKC*13; i += 256) Bs[i/13][100 + i%13] = 0.f;
    if (t < TQ) {
        int j = rowBase + t; int gq = 0; float iv = 0.f;
        if (j < Q) { gq = J.map ? J.map[j] : j; iv = 1.f / J.qn[gq]; }
        rowIdx[t] = gq; rowInv[t] = iv;
    }
    __syncthreads();

    int r0 = t >> 3, k4 = t & 7;
    const float4* aP0 = (const float4*)(J.A + (size_t)rowIdx[r0]*DIM) + k4;
    const float4* aP1 = (const float4*)(J.A + (size_t)rowIdx[r0+32]*DIM) + k4;
    int f1 = t, f2 = t+256, f3 = t+512, f4 = t+768;
    const float4* bP1 = (const float4*)(J.P + (size_t)(f1>>3)*DIM) + (f1&7);
    const float4* bP2 = (const float4*)(J.P + (size_t)(f2>>3)*DIM) + (f2&7);
    const float4* bP3 = (const float4*)(J.P + (size_t)(f3>>3)*DIM) + (f3&7);
    const float4* bP4 = (f4 < 800) ? (const float4*)(J.P + (size_t)(f4>>3)*DIM) + (f4&7) : bP1;
    bool act4 = (f4 < 800);

    float acc[4][7];
    #pragma unroll
    for (int i = 0; i < 4; i++)
        #pragma unroll
        for (int jj = 0; jj < 7; jj++) acc[i][jj] = 0.f;

    float4 pa0 = aP0[0], pa1 = aP1[0];
    float4 pb1 = bP1[0], pb2 = bP2[0], pb3 = bP3[0], pb4 = act4 ? bP4[0] : make_float4(0,0,0,0);

    for (int k0 = 0; k0 < DIM; k0 += TKC) {
        As4[r0][k4] = pa0; As4[r0+32][k4] = pa1;
        {
            int kb = (f1&7)*4, c = f1>>3;
            Bs[kb+0][c]=pb1.x; Bs[kb+1][c]=pb1.y; Bs[kb+2][c]=pb1.z; Bs[kb+3][c]=pb1.w;
            kb = (f2&7)*4; c = f2>>3;
            Bs[kb+0][c]=pb2.x; Bs[kb+1][c]=pb2.y; Bs[kb+2][c]=pb2.z; Bs[kb+3][c]=pb2.w;
            kb = (f3&7)*4; c = f3>>3;
            Bs[kb+0][c]=pb3.x; Bs[kb+1][c]=pb3.y; Bs[kb+2][c]=pb3.z; Bs[kb+3][c]=pb3.w;
            if (act4) {
                kb = (f4&7)*4; c = f4>>3;
                Bs[kb+0][c]=pb4.x; Bs[kb+1][c]=pb4.y; Bs[kb+2][c]=pb4.z; Bs[kb+3][c]=pb4.w;
            }
        }
        __syncthreads();
        if (k0 + TKC < DIM) {
            int off = (k0 + TKC) >> 2;
            pa0 = aP0[off]; pa1 = aP1[off];
            pb1 = bP1[off]; pb2 = bP2[off]; pb3 = bP3[off];
            if (act4) pb4 = bP4[off];
        }
        #pragma unroll
        for (int kk4 = 0; kk4 < 8; kk4++) {
            float4 A0 = As4[ty*4+0][kk4], A1 = As4[ty*4+1][kk4];
            float4 A2 = As4[ty*4+2][kk4], A3 = As4[ty*4+3][kk4];
            float a0v[4] = {A0.x,A0.y,A0.z,A0.w};
            float a1v[4] = {A1.x,A1.y,A1.z,A1.w};
            float a2v[4] = {A2.x,A2.y,A2.z,A2.w};
            float a3v[4] = {A3.x,A3.y,A3.z,A3.w};
            #pragma unroll
            for (int s = 0; s < 4; s++) {
                const float* br = &Bs[kk4*4+s][tx*7];
                #pragma unroll
                for (int jj = 0; jj < 7; jj++) {
                    float b = br[jj];
                    acc[0][jj] += a0v[s]*b;
                    acc[1][jj] += a1v[s]*b;
                    acc[2][jj] += a2v[s]*b;
                    acc[3][jj] += a3v[s]*b;
                }
            }
        }
        __syncthreads();
    }

    float colssq[7];
    #pragma unroll
    for (int jj = 0; jj < 7; jj++) colssq[jj] = 0.f;
    #pragma unroll
    for (int i = 0; i < 4; i++) {
        int j = rowBase + ty*4 + i;
        float iv = rowInv[ty*4 + i];
        float v[7];
        #pragma unroll
        for (int jj = 0; jj < 7; jj++) { v[jj] = acc[i][jj]*iv; colssq[jj] += v[jj]*v[jj]; }
        if (j < Q) {
            if (J.transC) {
                #pragma unroll
                for (int jj = 0; jj < 7; jj++) {
                    int c = tx*7 + jj;
                    if (c < WAY) J.C[(size_t)c*NQ + j] = v[jj];
                }
            } else {
                #pragma unroll
                for (int jj = 0; jj < 7; jj++) {
                    int c = tx*7 + jj;
                    if (c < WAY) J.C[(size_t)j*WAY + c] = v[jj];
                }
            }
        }
    }
    #pragma unroll
    for (int jj = 0; jj < 7; jj++) tmp[ty*112 + tx*7+jj] = colssq[jj];
    __syncthreads();
    if (t < 112) {
        float s = 0.f;
        #pragma unroll
        for (int r = 0; r < 16; r++) s += tmp[r*112 + t];
        J.part[(size_t)t*NT + tb] = s;
    }
}

// ---- reduce partials -> scale ----
__global__ void k_colreduce(JSet js, const float* __restrict__ tp,
                            int useSc2, int fixedNT) {
    int job = blockIdx.x, t = threadIdx.x;
    if (t >= WAY) return;
    int nT = fixedNT ? fixedNT : (*js.cnt[job] + TQ - 1) / TQ;
    const float* p = js.part[job] + (size_t)t*NT;
    float s = 0.f;
    #pragma unroll 16
    for (int tb = 0; tb < nT; tb++) s += p[tb];
    float* o = useSc2 ? js.sc2[job] : js.sc1[job];
    o[t] = (*tp) / (sqrtf(s) + 1e-6f);
}

// ------- merged subset colnorm partials + partition + weights (+ticket reset) -------
__global__ __launch_bounds__(1024) void k_subpartition(
    const float* __restrict__ Gr, const float* __restrict__ Gd,
    const float* __restrict__ ar, const float* __restrict__ ad,
    const float* __restrict__ rr, const float* __restrict__ rd,
    float* __restrict__ part,
    int* __restrict__ resI, int* __restrict__ dctI,
    int* __restrict__ cnts, int* __restrict__ tick, float* __restrict__ out)
{
    int t = threadIdx.x;
    if (blockIdx.y < 2) {
        if (t >= 128) return;
        int tile = blockIdx.x, s = blockIdx.y;
        int c = t;
        const float* G = s ? Gd : Gr;
        float sR = 0.f, sD = 0.f;
        int j0 = tile * TQ;
        int jend = j0 + TQ; if (jend > NQ) jend = NQ;
        for (int j = j0; j < jend; j++) {
            float diff = ar[j] - ad[j] + rr[j] - rd[j];
            float v = (c < WAY) ? G[(size_t)j*WAY + c] : 0.f;
            float v2 = v*v;
            if (diff > 0.f) sR += v2;
            if (diff < 0.f) sD += v2;
        }
        if (c < 112) {
            part[(size_t)(2*s+0)*SLAB + (size_t)c*NT + tile] = sR;
            part[(size_t)(2*s+1)*SLAB + (size_t)c*NT + tile] = sD;
        }
        return;
    }
    if (blockIdx.x != 0) return;
    __shared__ int ws[32];
    __shared__ int rb, Rs;
    if (t < 2) tick[t] = 0;
    if (t == 0) rb = 0;
    __syncthreads();
    for (int j0 = 0; j0 < NQ; j0 += 1024) {
        int j = j0 + t, f = 0;
        if (j < NQ) f = ((ar[j]-ad[j]+rr[j]-rd[j]) > 0.f);
        int tot; int ex = bScan1024(f, &tot, ws);
        if (f) { int sl = rb + ex; resI[sl] = j; out[2+sl] = (float)j; }
        __syncthreads();
        if (t == 0) rb += tot;
        __syncthreads();
    }
    if (t == 0) { Rs = rb; cnts[0] = rb; rb = 0; }
    __syncthreads();
    int R = Rs;
    for (int j0 = 0; j0 < NQ; j0 += 1024) {
        int j = j0 + t, f = 0;
        if (j < NQ) f = ((ar[j]-ad[j]+rr[j]-rd[j]) < 0.f);
        int tot; int ex = bScan1024(f, &tot, ws);
        if (f) { int sl = rb + ex; dctI[sl] = j; out[2+R+sl] = (float)j; }
        __syncthreads();
        if (t == 0) rb += tot;
        __syncthreads();
    }
    if (t == 0) cnts[1] = rb;
    __syncthreads();
    int base = 2 + R + rb;
    for (int q = t; q < NQ; q += 1024) {
        float a = ar[q], b = ad[q], den = fmaxf(a+b, 1e-8f);
        out[base + q] = a/den;
        out[base + NQ + q] = b/den;
    }
}

// ------- cert with fused scale reduction (early-exit for fully-OOB blocks) -------
__global__ void k_cert(JSet js, const float* __restrict__ tp) {
    int job = blockIdx.y;
    int Q = *js.cnt[job];
    if (blockIdx.x > 0 && (int)(blockIdx.x*blockDim.x) >= Q) return;
    __shared__ float ssc[WAY];
    int t = threadIdx.x;
    if (t < WAY) {
        const float* p = js.part[job] + (size_t)t*NT;
        float s = 0.f;
        #pragma unroll 16
        for (int tb = 0; tb < NT; tb++) s += p[tb];
        float sc = (*tp) / (sqrtf(s) + 1e-6f);
        ssc[t] = sc;
        if (blockIdx.x == 0) js.sc1[job][t] = sc;
    }
    __syncthreads();
    int j = blockIdx.x*blockDim.x + t;
    if (j >= Q) return;
    const int* map = js.map[job];
    int r = map ? map[j] : j;
    const float* row = js.G[job] + (size_t)r*WAY;
    float best = -3.4e38f;
    #pragma unroll 4
    for (int c = 0; c < WAY; c++) { float v = row[c]*ssc[c]; if (v > best) best = v; }
    js.cert[job][j] = best;
}

// ------- radix top-k: smem hist passes + 4-wide selection + fused pseudo -------
__global__ __launch_bounds__(1024) void k_topk(JSet js) {
    int job = blockIdx.x, t = threadIdx.x;
    const float* cert = js.cert[job];
    __shared__ unsigned hist[2048];
    __shared__ int ws[32];
    __shared__ unsigned shP, shM;
    __shared__ int shR;
    __shared__ float ssc[WAY];
    int Q = *js.cnt[job];
    int k = (Q < KSEL) ? Q : KSEL;
    if (t == 0) { shP = 0u; shM = 0u; shR = k; }
    __syncthreads();
    for (int pass = 0; pass < 3; pass++) {
        int shift = (pass == 0) ? 21 : ((pass == 1) ? 10 : 0);
        int nb = (pass == 2) ? 1024 : 2048;
        for (int i = t; i < 2048; i += 1024) hist[i] = 0u;
        __syncthreads();
        unsigned pfx = shP, msk = shM;
        int rem = shR;
        for (int j = t; j < Q; j += 1024) {
            unsigned u = okey(cert[j]);
            if ((u & msk) == pfx) atomicAdd(&hist[(u >> shift) & (nb-1)], 1u);
        }
        __syncthreads();
        int i0 = nb - 1 - 2*t, i1 = nb - 2 - 2*t;
        int h0 = (i0 >= 0) ? (int)hist[i0] : 0;
        int h1 = (i1 >= 0) ? (int)hist[i1] : 0;
        int tot; int ex = bScan1024(h0 + h1, &tot, ws);
        if (i0 >= 0 && ex < rem && ex + h0 >= rem) {
            shP = pfx | ((unsigned)i0 << shift);
            shM = msk | ((unsigned)(nb-1) << shift);
            shR = rem - ex;
        } else if (i1 >= 0 && ex + h0 < rem && ex + h0 + h1 >= rem) {
            shP = pfx | ((unsigned)i1 << shift);
            shM = msk | ((unsigned)(nb-1) << shift);
            shR = rem - ex - h0;
        }
        __syncthreads();
    }
    unsigned Kk = shP; int rem = shR;
    int eqB = 0, seB = 0;
    for (int j0 = 0; j0 < Q; j0 += 4096) {
        int jb = j0 + t*4;
        int gi[4], ei[4]; float vi[4];
        int gcnt = 0, ecnt = 0;
        #pragma unroll
        for (int i = 0; i < 4; i++) {
            int j = jb + i;
            gi[i] = 0; ei[i] = 0; vi[i] = 0.f;
            if (j < Q) {
                float v = cert[j];
                unsigned u = okey(v);
                gi[i] = (u > Kk); ei[i] = (u == Kk); vi[i] = v;
            }
            gcnt += gi[i]; ecnt += ei[i];
        }
        int tot; int ex = bScan1024(gcnt | (ecnt << 13), &tot, ws);
        int gEx = ex & 0x1FFF, eEx = ex >> 13;
        int gTot = tot & 0x1FFF, eTot = tot >> 13;
        int c0 = rem - eqB; if (c0 < 0) c0 = 0;
        int gP = 0, eP = 0;
        #pragma unroll
        for (int i = 0; i < 4; i++) {
            int er = eEx + eP;
            int eqSelB = (er < c0) ? er : c0;
            int sel = gi[i] | (ei[i] & (er < c0));
            if (sel) {
                int sl = seB + gEx + gP + eqSelB;
                js.seli[job][sl] = jb + i;
                js.selv[job][sl] = vi[i];
            }
            gP += gi[i]; eP += ei[i];
        }
        eqB += eTot;
        seB += gTot + ((eTot < c0) ? eTot : c0);
    }
    if (t == 0) *js.selk[job] = k;
    if (t < WAY) ssc[t] = js.sc1[job][t];
    __syncthreads();
    const int* map = js.map[job];
    for (int i = t; i < k; i += 1024) {
        int j = js.seli[job][i];
        int r = map ? map[j] : j;
        const float* row = js.G[job] + (size_t)r*WAY;
        float best = -3.4e38f; int bc = 0;
        for (int c = 0; c < WAY; c++) { float v = row[c]*ssc[c]; if (v > best) { best = v; bc = c; } }
        js.pse[job][i] = bc;
    }
}

// ------- refined proto: match compaction + DIM-half split (bitwise-safe) -------
__global__ void k_proto1(JSet js) {
    int job = blockIdx.y;
    int c = blockIdx.x >> 1, dh = (blockIdx.x & 1) * 1024;
    int K = *js.selk[job];
    __shared__ int mQ[KSEL];
    __shared__ float mCf[KSEL];
    __shared__ int ws[32];
    __shared__ int base;
    int t = threadIdx.x;
    if (t == 0) base = 0;
    __syncthreads();
    const int* map = js.map[job];
    for (int i0 = 0; i0 < K; i0 += 256) {
        int i = i0 + t;
        int m = 0, gq = 0; float cf = 0.f;
        if (i < K && js.pse[job][i] == c) {
            m = 1;
            int j = js.seli[job][i];
            gq = map ? map[j] : j;
            cf = js.selv[job][i] / ((float)K * js.qn[job][gq]);
        }
        int tot; int ex = bScan256(m, &tot, ws);
        if (m) { mQ[base + ex] = gq; mCf[base + ex] = cf; }
        __syncthreads();
        if (t == 0) base += tot;
        __syncthreads();
    }
    int nM = base;
    const float* P0 = js.P0[job] + (size_t)c*DIM + dh;
    float* P1 = js.P1[job] + (size_t)c*DIM + dh;
    const float* A = js.A[job];
    float acc[4];
    #pragma unroll
    for (int kq = 0; kq < 4; kq++) acc[kq] = P0[t + 256*kq];
    for (int m = 0; m < nM; m++) {
        float cf = mCf[m];
        const float* a = A + (size_t)mQ[m]*DIM + dh;
        #pragma unroll
        for (int kq = 0; kq < 4; kq++) acc[kq] += cf * a[t + 256*kq];
    }
    #pragma unroll
    for (int kq = 0; kq < 4; kq++) P1[t + 256*kq] = acc[kq];
}

// ---------------- row softmax stats ----------------
__global__ void k_rowstats(RSJ r) {
    int job = blockIdx.y;
    __shared__ float ssc[WAY];
    if (threadIdx.x < WAY) ssc[threadIdx.x] = r.sc[job][threadIdx.x];
    __syncthreads();
    int row = blockIdx.x*8 + (threadIdx.x >> 5);
    int lane = threadIdx.x & 31;
    if (row >= NQ) return;
    const float* L = r.L[job] + (size_t)row*WAY;
    float lv[4];
    int nc = 0;
    #pragma unroll
    for (int i = 0; i < 4; i++) {
        int c = lane + 32*i;
        if (c < WAY) { lv[i] = L[c]*ssc[c]; nc = i+1; } else lv[i] = 0.f;
    }
    float m = -3.4e38f;
    for (int i = 0; i < nc; i++) m = fmaxf(m, lv[i]);
    #pragma unroll
    for (int o = 16; o; o >>= 1) m = fmaxf(m, __shfl_xor_sync(~0u, m, o));
    float ex[4];
    float Z = 0.f;
    for (int i = 0; i < nc; i++) { ex[i] = expf(lv[i] - m); Z += ex[i]; }
    #pragma unroll
    for (int o = 16; o; o >>= 1) Z += __shfl_xor_sync(~0u, Z, o);
    float rel = 0.f;
    for (int i = 0; i < nc; i++) {
        float p = ex[i] / Z;
        rel += p * logf(p + 1e-10f);
    }
    #pragma unroll
    for (int o = 16; o; o >>= 1) rel += __shfl_xor_sync(~0u, rel, o);
    if (lane == 0) { r.absc[job][row] = m; r.relc[job][row] = rel; }
}

// ------- per-class KL (transposed L) + fused last-block finalize -------
__global__ void k_classkl(KLJ kj) {
    int pr = blockIdx.y, c = blockIdx.x;
    int Q = *kj.cnt[pr];
    int nT = (Q + TQ - 1) / TQ;
    __shared__ float shsl[2];
    __shared__ float red[256];
    if (threadIdx.x < 2) {
        const float* p = (threadIdx.x ? kj.pl[pr] : kj.ph[pr]) + (size_t)c*NT;
        float s = 0.f;
        #pragma unroll 16
        for (int tb = 0; tb < nT; tb++) s += p[tb];
        shsl[threadIdx.x] = (*kj.tp) / (sqrtf(s) + 1e-6f);
    }
    __syncthreads();
    float sh = shsl[0], sl = shsl[1];
    const float* Lh = kj.Lh[pr] + (size_t)c*NQ;
    const float* Ll = kj.Ll[pr] + (size_t)c*NQ;
    float mh = -3.4e38f, ml = -3.4e38f;
    for (int j = threadIdx.x; j < Q; j += 256) {
        mh = fmaxf(mh, Lh[j]*sh);
        ml = fmaxf(ml, Ll[j]*sl);
    }
    mh = bMax256(mh, red); ml = bMax256(ml, red);
    float Zh = 0.f, Zl = 0.f;
    for (int j = threadIdx.x; j < Q; j += 256) {
        Zh += expf(Lh[j]*sh - mh);
        Zl += expf(Ll[j]*sl - ml);
    }
    Zh = bSum256(Zh, red); Zl = bSum256(Zl, red);
    float lZl = logf(Zl), s = 0.f;
    for (int j = threadIdx.x; j < Q; j += 256) {
        float lh = Lh[j]*sh, ll = Ll[j]*sl;
        float p = expf(lh - mh) / Zh;
        s += p * (logf(p) - (ll - ml - lZl));
    }
    s = bSum256(s, red);
    __shared__ int isLast;
    if (threadIdx.x == 0) {
        kj.kl[pr][c] = s;
        __threadfence();
        int old = atomicAdd(&kj.tick[pr], 1);
        isLast = (old == WAY - 1);
    }
    __syncthreads();
    if (!isLast) return;
    __threadfence();
    float fs = 0.f;
    for (int cc = threadIdx.x; cc < WAY; cc += 256) fs += kj.kl[pr][cc];
    fs = bSum256(fs, red);
    float sw = 0.f;
    for (int j = threadIdx.x; j < Q; j += 256) sw += kj.absc[pr][kj.idx[pr][j]];
    sw = bSum256(sw, red);
    if (threadIdx.x == 0) {
        float w0 = (Q > 0) ? kj.absc[pr][kj.idx[pr][0]] : 0.f;
        *kj.slot[pr] = (*kj.tsc[pr]) * (w0 * fs / (sw + 1e-8f));
    }
}

// ---------------- host ----------------
extern "C" void kernel_launch(void* const* d_in, const int* in_sizes, int n_in,
                              void* d_out, int out_size)
{
    const float* x_shot    = (const float*)d_in[0];
    const float* x_query   = (const float*)d_in[1];
    const float* dct_shot  = (const float*)d_in[2];
    const float* dct_query = (const float*)d_in[3];
    const float* tp        = (const float*)d_in[4];
    const float* temp      = (const float*)d_in[5];
    const float* temp_dct  = (const float*)d_in[6];
    float* out = (float*)d_out;

    float* B = nullptr; int* IB = nullptr; int* FC = nullptr;
    cudaGetSymbolAddress((void**)&B, g_buf);
    cudaGetSymbolAddress((void**)&IB, g_ibuf);
    cudaGetSymbolAddress((void**)&FC, g_fullCnt);

    float* P0 = B + O_P0;     float* P1 = B + O_P1;
    float* QN = B + O_QN;     float* G = B + O_G;
    float* L = B + O_L;       float* CERT = B + O_CERT;
    float* SELV = B + O_SELV;
    float* ABSR = B + O_STAT; float* ABSD = ABSR + NQ;
    float* RELR = ABSD + NQ;  float* RELD = RELR + NQ;
    float* SC1 = B + O_SC1;   float* SC2 = B + O_SC2;
    float* KL = B + O_KL;     float* PART = B + O_PART;
    int* RES = IB + IO_RES;   int* DCT = IB + IO_DCT;
    int* SELI = IB + IO_SELI; int* PSE = IB + IO_PSE;
    int* SELK = IB + IO_SELK; int* CNTS = IB + IO_CNTS;
    int* TICK = IB + IO_TICK;
    const int* CR = CNTS;     const int* CD = CNTS + 1;

    const float* Aq[2] = { x_query, dct_query };

    // -------- phase 1 --------
    JSet j1 = {};
    for (int s = 0; s < 2; s++) {
        j1.A[s] = Aq[s]; j1.qn[s] = QN + s*NQ;
        j1.P0[s] = P0 + s*SLP; j1.G[s] = G + (size_t)s*NQ*WAY;
        j1.map[s] = nullptr; j1.cnt[s] = FC;
        j1.P1[s] = P1 + s*SLP;
        j1.cert[s] = CERT + s*NQ; j1.selv[s] = SELV + s*KSEL;
        j1.sc1[s] = SC1 + s*WAY; j1.sc2[s] = SC2 + s*WAY;
        j1.seli[s] = SELI + s*KSEL; j1.selk[s] = SELK + s; j1.pse[s] = PSE + s*KSEL;
        j1.part[s] = PART + (size_t)s*SLAB;
    }
    k_init<<<dim3(WAY + NQ, 2), 256>>>(x_shot, dct_shot, x_query, dct_query,
                                       P0, P0 + SLP, QN, QN + NQ);

    GJobs g1 = {};
    for (int s = 0; s < 2; s++)
        g1.j[s] = { Aq[s], QN + s*NQ, P0 + s*SLP, G + (size_t)s*NQ*WAY,
                    PART + (size_t)s*SLAB, nullptr, FC, 0 };
    k_gemm<<<2*NT, 256>>>(g1);
    k_cert<<<dim3((NQ+255)/256, 2), 256>>>(j1, tp);
    k_topk<<<2, 1024>>>(j1);
    k_proto1<<<dim3(2*WAY, 2), 256>>>(j1);

    GJobs g2 = {};
    for (int s = 0; s < 2; s++)
        g2.j[s] = { Aq[s], QN + s*NQ, P1 + s*SLP, L + (size_t)s*NQ*WAY,
                    PART + (size_t)s*SLAB, nullptr, FC, 0 };
    k_gemm<<<2*NT, 256>>>(g2);
    k_colreduce<<<2, 128>>>(j1, tp, 1, 0);

    RSJ rs;
    rs.L[0] = L; rs.L[1] = L + (size_t)NQ*WAY;
    rs.sc[0] = SC2; rs.sc[1] = SC2 + WAY;
    rs.absc[0] = ABSR; rs.absc[1] = ABSD;
    rs.relc[0] = RELR; rs.relc[1] = RELD;
    k_rowstats<<<dim3((NQ+7)/8, 2), 256>>>(rs);

    k_subpartition<<<dim3(NT, 3), 1024>>>(G, G + (size_t)NQ*WAY,
                                          ABSR, ABSD, RELR, RELD,
                                          PART, RES, DCT, CNTS, TICK, out);

    // -------- phase 3: jobs 0 x/RES  1 dct/RES  2 dct/DCT  3 x/DCT --------
    int src[4] = { 0, 1, 1, 0 };
    const int* mp[4] = { RES, RES, DCT, DCT };
    const int* cn[4] = { CR, CR, CD, CD };
    int slab[4] = { 0, 2, 3, 1 };
    JSet j3 = {};
    for (int s = 0; s < 4; s++) {
        int u = src[s];
        j3.A[s] = Aq[u]; j3.qn[s] = QN + u*NQ;
        j3.P0[s] = P0 + u*SLP; j3.G[s] = G + (size_t)u*NQ*WAY;
        j3.map[s] = mp[s]; j3.cnt[s] = cn[s];
        j3.P1[s] = P1 + s*SLP;
        j3.cert[s] = CERT + s*NQ; j3.selv[s] = SELV + s*KSEL;
        j3.sc1[s] = SC1 + s*WAY; j3.sc2[s] = SC2 + s*WAY;
        j3.seli[s] = SELI + s*KSEL; j3.selk[s] = SELK + s; j3.pse[s] = PSE + s*KSEL;
        j3.part[s] = PART + (size_t)slab[s]*SLAB;
    }
    k_cert<<<dim3((NQ+255)/256, 4), 256>>>(j3, tp);
    k_topk<<<4, 1024>>>(j3);
    k_proto1<<<dim3(2*WAY, 4), 256>>>(j3);

    GJobs g3 = {};
    for (int s = 0; s < 4; s++)
        g3.j[s] = { j3.A[s], j3.qn[s], P1 + s*SLP, L + (size_t)s*NQ*WAY,
                    PART + (size_t)s*SLAB, mp[s], cn[s], 1 };
    k_gemm<<<4*NT, 256>>>(g3);

    KLJ kj;
    kj.Lh[0] = L;                     kj.Ll[0] = L + (size_t)NQ*WAY;
    kj.ph[0] = PART;                  kj.pl[0] = PART + (size_t)1*SLAB;
    kj.cnt[0] = CR; kj.kl[0] = KL;
    kj.Lh[1] = L + (size_t)2*NQ*WAY;  kj.Ll[1] = L + (size_t)3*NQ*WAY;
    kj.ph[1] = PART + (size_t)2*SLAB; kj.pl[1] = PART + (size_t)3*SLAB;
    kj.cnt[1] = CD; kj.kl[1] = KL + WAY;
    kj.tp = tp;
    kj.absc[0] = ABSR; kj.idx[0] = RES; kj.tsc[0] = temp_dct; kj.slot[0] = out + 1;
    kj.absc[1] = ABSD; kj.idx[1] = DCT; kj.tsc[1] = temp;     kj.slot[1] = out + 0;
    kj.tick = TICK;
    k_classkl<<<dim3(WAY,2), 256>>>(kj);
}